// round 1
// baseline (speedup 1.0000x reference)
#include <cuda_runtime.h>
#include <stdint.h>

#define HH 512
#define WW 512
#define HW (HH*WW)
#define NS 8            // samples
#define NIMG 16         // samples * {pred, mask}
#define KP 1024         // points per set
#define T_MST 256
#define NPT (KP / T_MST)

// ---------------- scratch (static device globals; no allocation) ----------------
__device__ float          g_bin[NIMG * HW];       // binarized images (0.0/1.0)
__device__ unsigned char  g_flag[NIMG * HW];      // lbp < THR flags
__device__ float2         g_pts[NIMG][KP];        // selected points (r, c)
__device__ int2           g_edges[NIMG][KP - 1];  // MST edges (src, j) in order
__device__ float          g_ls[NS];               // per-sample loss

// ---------------- 1) binarize ----------------
__global__ void binarize_kernel(const float* __restrict__ mo, const float* __restrict__ lb) {
    int gid = blockIdx.x * blockDim.x + threadIdx.x;
    if (gid >= NS * HW) return;
    int s = gid >> 18;           // / HW
    int p = gid & (HW - 1);
    g_bin[(2 * s) * HW + p]     = (mo[gid] > 0.0f) ? 1.0f : 0.0f;   // sigmoid(x)>0.5 <=> x>0
    g_bin[(2 * s + 1) * HW + p] = (lb[gid] > 0.5f) ? 1.0f : 0.0f;
}

// ---------------- 2) uniform LBP (P=8, R=1, bilinear, edge-clamped) ----------------
__global__ void lbp_kernel() {
    // dr = round(-sin(2*pi*k/8), 8), dc = round(cos(2*pi*k/8), 8) cast to f32 (same as JAX)
    const float DR[8] = { (float)-0.0, (float)-0.70710678, (float)-1.0, (float)-0.70710678,
                          (float)-0.0, (float) 0.70710678, (float) 1.0, (float) 0.70710678 };
    const float DC[8] = { (float) 1.0, (float) 0.70710678, (float) 0.0, (float)-0.70710678,
                          (float)-1.0, (float)-0.70710678, (float)-0.0, (float) 0.70710678 };

    int gid = blockIdx.x * blockDim.x + threadIdx.x;
    if (gid >= NIMG * HW) return;
    int img = gid >> 18;
    int p = gid & (HW - 1);
    int row = p >> 9;
    int col = p & 511;
    const float* __restrict__ b = g_bin + img * HW;

    float center = b[p];
    float frow = (float)row;
    float fcol = (float)col;

    int bits[8];
#pragma unroll
    for (int k = 0; k < 8; k++) {
        float rr = __fadd_rn(frow, DR[k]);
        float cc = __fadd_rn(fcol, DC[k]);
        float r0 = floorf(rr);
        float c0 = floorf(cc);
        float fr = __fsub_rn(rr, r0);
        float fc = __fsub_rn(cc, c0);
        int r0i = min(max((int)r0, 0), HH - 1);
        int r1i = min(r0i + 1, HH - 1);
        int c0i = min(max((int)c0, 0), WW - 1);
        int c1i = min(c0i + 1, WW - 1);
        float g00 = __ldg(b + ((r0i << 9) | c0i));
        float g01 = __ldg(b + ((r0i << 9) | c1i));
        float g10 = __ldg(b + ((r1i << 9) | c0i));
        float g11 = __ldg(b + ((r1i << 9) | c1i));
        // exact, non-contracted replica of:
        // (1-fr)*((1-fc)*g00 + fc*g01) + fr*((1-fc)*g10 + fc*g11)
        float fc1 = __fsub_rn(1.0f, fc);
        float fr1 = __fsub_rn(1.0f, fr);
        float top = __fadd_rn(__fmul_rn(fc1, g00), __fmul_rn(fc, g01));
        float bot = __fadd_rn(__fmul_rn(fc1, g10), __fmul_rn(fc, g11));
        float sv  = __fadd_rn(__fmul_rn(fr1, top), __fmul_rn(fr, bot));
        bits[k] = (__fsub_rn(sv, center) >= 0.0f) ? 1 : 0;
    }

    int ssum = 0, changes = 0;
#pragma unroll
    for (int k = 0; k < 8; k++) {
        ssum += bits[k];
        int prev = bits[(k + 7) & 7];
        changes += (bits[k] != prev) ? 1 : 0;
    }
    // lbp = (changes<=2) ? ssum : 9 ;  flag = lbp < 5
    g_flag[gid] = (changes <= 2 && ssum < 5) ? 1 : 0;
}

// ---------------- 3) ordered compaction: first KP true pixels (row-major), zero-padded ----------------
__global__ void __launch_bounds__(1024) select_kernel() {
    int img = blockIdx.x;
    const unsigned char* __restrict__ m = g_flag + img * HW;
    __shared__ int warpcnt[32];
    __shared__ int warpoff[32];
    __shared__ int s_base;

    int tid = threadIdx.x;
    int lane = tid & 31;
    int w = tid >> 5;

    g_pts[img][tid] = make_float2(0.0f, 0.0f);   // zero-pad (valid=0 points)
    if (tid == 0) s_base = 0;
    __syncthreads();

    for (int chunk = 0; chunk < HW / 1024; chunk++) {
        int base = s_base;
        if (base >= KP) break;
        int p = chunk * 1024 + tid;
        int pred = m[p];
        unsigned bal = __ballot_sync(0xffffffffu, pred);
        if (lane == 0) warpcnt[w] = __popc(bal);
        __syncthreads();
        if (tid == 0) {
            int acc = 0;
            for (int i = 0; i < 32; i++) { warpoff[i] = acc; acc += warpcnt[i]; }
            s_base = base + acc;
        }
        __syncthreads();
        if (pred) {
            int rank = base + warpoff[w] + __popc(bal & ((1u << lane) - 1u));
            if (rank < KP)
                g_pts[img][rank] = make_float2((float)(p >> 9), (float)(p & 511));
        }
        __syncthreads();
    }
}

// ---------------- 4) Prim's MST (exact replica of reference semantics) ----------------
__global__ void __launch_bounds__(T_MST) mst_kernel() {
    int img = blockIdx.x;
    __shared__ float sx[KP];
    __shared__ float sy[KP];
    __shared__ unsigned long long warpbest[T_MST / 32];
    __shared__ int s_j;

    int tid = threadIdx.x;
    for (int i = tid; i < KP; i += T_MST) {
        float2 pt = g_pts[img][i];
        sx[i] = pt.x; sy[i] = pt.y;
    }
    __syncthreads();

    float mind[NPT];
    int   src[NPT];
    bool  intree[NPT];
    float x0 = sx[0], y0 = sy[0];
#pragma unroll
    for (int q = 0; q < NPT; q++) {
        int node = tid * NPT + q;
        float dx = sx[node] - x0, dy = sy[node] - y0;
        mind[q] = sqrtf(dx * dx + dy * dy);   // exact: integer d2 < 2^20, IEEE sqrt
        src[q] = 0;
        intree[q] = (node == 0);
    }

    for (int step = 0; step < KP - 1; step++) {
        unsigned long long best = 0xFFFFFFFFFFFFFFFFull;
#pragma unroll
        for (int q = 0; q < NPT; q++) {
            if (!intree[q]) {
                unsigned long long key =
                    ((unsigned long long)__float_as_uint(mind[q]) << 32) |
                    (unsigned)(tid * NPT + q);
                best = min(best, key);
            }
        }
#pragma unroll
        for (int off = 16; off; off >>= 1)
            best = min(best, __shfl_down_sync(0xffffffffu, best, off));
        if ((tid & 31) == 0) warpbest[tid >> 5] = best;
        __syncthreads();
        if (tid == 0) {
            unsigned long long bb = warpbest[0];
#pragma unroll
            for (int wv = 1; wv < T_MST / 32; wv++) bb = min(bb, warpbest[wv]);
            s_j = (int)(bb & 0xFFFFFFFFu);
        }
        __syncthreads();
        int j = s_j;
        float jx = sx[j], jy = sy[j];
        if ((j / NPT) == tid) {
            int q = j & (NPT - 1);
            g_edges[img][step] = make_int2(src[q], j);
            intree[q] = true;
        }
#pragma unroll
        for (int q = 0; q < NPT; q++) {
            if (!intree[q]) {
                int node = tid * NPT + q;
                float dx = sx[node] - jx, dy = sy[node] - jy;
                float d = sqrtf(dx * dx + dy * dy);
                if (d < mind[q]) { mind[q] = d; src[q] = j; }   // strict <, matches reference
            }
        }
    }
}

// ---------------- 5) per-sample loss ----------------
__device__ __forceinline__ float pdistf(float2 a, float2 b) {
    float dx = a.x - b.x, dy = a.y - b.y;
    return sqrtf(dx * dx + dy * dy);
}

__global__ void loss_kernel() {
    int s = blockIdx.x;
    const float2* Pp = g_pts[2 * s];
    const float2* Pm = g_pts[2 * s + 1];
    const int2*   Ep = g_edges[2 * s];
    const int2*   Em = g_edges[2 * s + 1];

    float accP = 0.0f, accM = 0.0f;
    for (int e = threadIdx.x; e < KP - 1; e += blockDim.x) {
        int2 ep = Ep[e];
        float d1 = pdistf(Pp[ep.x], Pp[ep.y]) - pdistf(Pm[ep.x], Pm[ep.y]);
        accP += d1 * d1;
        int2 em = Em[e];
        float d2 = pdistf(Pp[em.x], Pp[em.y]) - pdistf(Pm[em.x], Pm[em.y]);
        accM += d2 * d2;
    }
    __shared__ float rp[256], rm[256];
    int tid = threadIdx.x;
    rp[tid] = accP; rm[tid] = accM;
    __syncthreads();
    for (int w = 128; w; w >>= 1) {
        if (tid < w) { rp[tid] += rp[tid + w]; rm[tid] += rm[tid + w]; }
        __syncthreads();
    }
    if (tid == 0) g_ls[s] = sqrtf(rp[0]) + sqrtf(rm[0]);
}

__global__ void final_kernel(float* out) {
    float t = 0.0f;
    for (int i = 0; i < NS; i++) t += g_ls[i];
    out[0] = 0.1f * t / 8.0f;
}

// ---------------- launch ----------------
extern "C" void kernel_launch(void* const* d_in, const int* in_sizes, int n_in,
                              void* d_out, int out_size) {
    const float* model_output = (const float*)d_in[1];
    const float* labels       = (const float*)d_in[2];
    float* out = (float*)d_out;

    binarize_kernel<<<(NS * HW + 255) / 256, 256>>>(model_output, labels);
    lbp_kernel<<<(NIMG * HW + 255) / 256, 256>>>();
    select_kernel<<<NIMG, 1024>>>();
    mst_kernel<<<NIMG, T_MST>>>();
    loss_kernel<<<NS, 256>>>();
    final_kernel<<<1, 1>>>(out);
}

// round 3
// speedup vs baseline: 3.0088x; 3.0088x over previous
#include <cuda_runtime.h>
#include <stdint.h>

#define HH 512
#define WW 512
#define HW (HH*WW)
#define NS 8            // samples
#define NIMG 16         // samples * {pred, mask}
#define KP 1024         // points per set
#define T_MST 256
#define NPT (KP / T_MST)   // 4 nodes per thread
#define UMAXV 0xFFFFFFFFu

// ---------------- scratch (static device globals; no allocation) ----------------
__device__ unsigned char  g_flag[NIMG * HW];      // lbp < THR flags
__device__ float2         g_pts[NIMG][KP];        // selected points (r, c) float
__device__ unsigned       g_pti[NIMG][KP];        // packed int coords (r<<16)|c
__device__ int2           g_edges[NIMG][KP - 1];  // MST edges (src, j)
__device__ float          g_ls[NS];               // per-sample loss

// ---------------- bilinear bit, exact non-contracted replica of XLA fp32 ops ---
__device__ __forceinline__ int bil(float fr, float fc,
                                   float g00, float g01, float g10, float g11,
                                   float c) {
    float fc1 = __fsub_rn(1.0f, fc);
    float fr1 = __fsub_rn(1.0f, fr);
    float top = __fadd_rn(__fmul_rn(fc1, g00), __fmul_rn(fc, g01));
    float bot = __fadd_rn(__fmul_rn(fc1, g10), __fmul_rn(fc, g11));
    float sv  = __fadd_rn(__fmul_rn(fr1, top), __fmul_rn(fr, bot));
    return (__fsub_rn(sv, c) >= 0.0f) ? 1 : 0;
}

// ---------------- 1) fused binarize + uniform LBP (P=8, R=1) -------------------
__global__ void lbp_kernel(const float* __restrict__ mo, const float* __restrict__ lb) {
    const float DR[8] = { -0.0f, -0.70710678f, -1.0f, -0.70710678f,
                          -0.0f,  0.70710678f,  1.0f,  0.70710678f };
    const float DC[8] = {  1.0f,  0.70710678f,  0.0f, -0.70710678f,
                          -1.0f, -0.70710678f, -0.0f,  0.70710678f };

    int gid = blockIdx.x * blockDim.x + threadIdx.x;
    if (gid >= NIMG * HW) return;
    const int img = gid >> 18;
    const int p = gid & (HW - 1);
    const int row = p >> 9, col = p & 511;
    const int s = img >> 1;
    const float* __restrict__ src = ((img & 1) == 0) ? (mo + s * HW) : (lb + s * HW);
    const float thr = ((img & 1) == 0) ? 0.0f : 0.5f;   // sigmoid(x)>0.5 <=> x>0

    int bits[8];
    const float frow = (float)row, fcol = (float)col;

    if (row >= 1 && row <= 510 && col >= 1 && col <= 510) {
        // interior fast path: preload binarized 3x3, static corner indices
        float v[3][3];
#pragma unroll
        for (int i = 0; i < 3; i++)
#pragma unroll
            for (int jj = 0; jj < 3; jj++)
                v[i][jj] = (__ldg(src + ((row - 1 + i) << 9) + (col - 1 + jj)) > thr) ? 1.0f : 0.0f;
        float c = v[1][1];
        // even k: integer offsets -> exact single-tap samples
        bits[0] = (v[1][2] >= c);
        bits[2] = (v[0][1] >= c);
        bits[4] = (v[1][0] >= c);
        bits[6] = (v[2][1] >= c);
        // odd k: bilinear with per-pixel fp32 fractional parts (matches XLA exactly)
        float rrm = __fadd_rn(frow, -0.70710678f);
        float rrp = __fadd_rn(frow,  0.70710678f);
        float ccm = __fadd_rn(fcol, -0.70710678f);
        float ccp = __fadd_rn(fcol,  0.70710678f);
        float frm = __fsub_rn(rrm, floorf(rrm));
        float frp = __fsub_rn(rrp, floorf(rrp));
        float fcm = __fsub_rn(ccm, floorf(ccm));
        float fcp = __fsub_rn(ccp, floorf(ccp));
        bits[1] = bil(frm, fcp, v[0][1], v[0][2], v[1][1], v[1][2], c);  // (-.707, +.707)
        bits[3] = bil(frm, fcm, v[0][0], v[0][1], v[1][0], v[1][1], c);  // (-.707, -.707)
        bits[5] = bil(frp, fcm, v[1][0], v[1][1], v[2][0], v[2][1], c);  // (+.707, -.707)
        bits[7] = bil(frp, fcp, v[1][1], v[1][2], v[2][1], v[2][2], c);  // (+.707, +.707)
    } else {
        // border: generic clamped path (exact replica)
        float center = (__ldg(src + p) > thr) ? 1.0f : 0.0f;
#pragma unroll
        for (int k = 0; k < 8; k++) {
            float rr = __fadd_rn(frow, DR[k]);
            float cc = __fadd_rn(fcol, DC[k]);
            float r0 = floorf(rr);
            float c0 = floorf(cc);
            float fr = __fsub_rn(rr, r0);
            float fc = __fsub_rn(cc, c0);
            int r0i = min(max((int)r0, 0), HH - 1);
            int r1i = min(r0i + 1, HH - 1);
            int c0i = min(max((int)c0, 0), WW - 1);
            int c1i = min(c0i + 1, WW - 1);
            float g00 = (__ldg(src + ((r0i << 9) | c0i)) > thr) ? 1.0f : 0.0f;
            float g01 = (__ldg(src + ((r0i << 9) | c1i)) > thr) ? 1.0f : 0.0f;
            float g10 = (__ldg(src + ((r1i << 9) | c0i)) > thr) ? 1.0f : 0.0f;
            float g11 = (__ldg(src + ((r1i << 9) | c1i)) > thr) ? 1.0f : 0.0f;
            bits[k] = bil(fr, fc, g00, g01, g10, g11, center);
        }
    }

    int ssum = 0, changes = 0;
#pragma unroll
    for (int k = 0; k < 8; k++) {
        ssum += bits[k];
        changes += (bits[k] != bits[(k + 7) & 7]) ? 1 : 0;
    }
    g_flag[gid] = (changes <= 2 && ssum < 5) ? 1 : 0;  // lbp < THR(=5)
}

// ---------------- 2) ordered compaction: 3-phase scan --------------------------
__global__ void __launch_bounds__(1024) select_kernel() {
    const int img = blockIdx.x;
    __shared__ int s_wtot[32];
    __shared__ int s_woff[32];
    const int tid = threadIdx.x, lane = tid & 31, wrp = tid >> 5;

    // zero-pad outputs (ordered before emission by the two barriers below)
    g_pts[img][tid] = make_float2(0.0f, 0.0f);
    g_pti[img][tid] = 0u;

    // phase 1: each thread counts its 256-byte span (row-major contiguous)
    const uint4* __restrict__ m4 = (const uint4*)(g_flag + img * HW);
    unsigned ucnt = 0u;
    const int b0 = tid * 16;
#pragma unroll
    for (int i = 0; i < 16; i++) {
        uint4 x = m4[b0 + i];
        ucnt = __dp4a(x.x, 0x01010101u, ucnt);
        ucnt = __dp4a(x.y, 0x01010101u, ucnt);
        ucnt = __dp4a(x.z, 0x01010101u, ucnt);
        ucnt = __dp4a(x.w, 0x01010101u, ucnt);
    }
    int cnt = (int)ucnt;
    // phase 2: block-wide exclusive prefix
    int incl = cnt;
#pragma unroll
    for (int d = 1; d < 32; d <<= 1) {
        int n = __shfl_up_sync(0xffffffffu, incl, d);
        if (lane >= d) incl += n;
    }
    if (lane == 31) s_wtot[wrp] = incl;
    __syncthreads();
    if (wrp == 0) {
        int t = s_wtot[lane];
        int ti = t;
#pragma unroll
        for (int d = 1; d < 32; d <<= 1) {
            int n = __shfl_up_sync(0xffffffffu, ti, d);
            if (lane >= d) ti += n;
        }
        s_woff[lane] = ti - t;
    }
    __syncthreads();
    int rank = s_woff[wrp] + (incl - cnt);
    // phase 3: ordered emission
    if (rank < KP && cnt > 0) {
        const unsigned char* __restrict__ mb = g_flag + img * HW + tid * 256;
        const int p0 = tid * 256;
        for (int i = 0; i < 256 && rank < KP; i++) {
            if (mb[i]) {
                int pp = p0 + i;
                int r = pp >> 9, c = pp & 511;
                g_pts[img][rank] = make_float2((float)r, (float)c);
                g_pti[img][rank] = ((unsigned)r << 16) | (unsigned)c;
                rank++;
            }
        }
    }
}

// ---------------- 3) Prim's MST, integer-key, sqrt-free ------------------------
// key = d2*1024 + idx  (d2 <= 522242, so key < 2^30): u32 min == (dist, first-idx)
// argmin, exactly matching the reference's float sqrt ordering (sqrt injective
// on exact integer d2 in this range).
__global__ void __launch_bounds__(T_MST) mst_kernel() {
    const int img = blockIdx.x;
    __shared__ unsigned s_xy[KP];
    __shared__ int s_src[KP];
    __shared__ unsigned s_red[2][8];

    const int tid = threadIdx.x;
    const int lane = tid & 31;
    const int wrp = tid >> 5;

    for (int i = tid; i < KP; i += T_MST) {
        s_xy[i] = g_pti[img][i];
        s_src[i] = 0;
    }
    __syncthreads();

    int px[NPT], py[NPT];
    unsigned key[NPT];
    bool in0 = false, in1 = false, in2 = false, in3 = false;
    const int base = tid * NPT;
    {
        const unsigned xy0 = s_xy[0];
        const int jx = (int)(xy0 >> 16), jy = (int)(xy0 & 0xffffu);
#pragma unroll
        for (int q = 0; q < NPT; q++) {
            unsigned v = s_xy[base + q];
            px[q] = (int)(v >> 16); py[q] = (int)(v & 0xffffu);
            int dx = px[q] - jx, dy = py[q] - jy;
            key[q] = (unsigned)(dx * dx + dy * dy) * 1024u + (unsigned)(base + q);
        }
    }
    if (tid == 0) { in0 = true; key[0] = UMAXV; }
    unsigned lmin = UMAXV;
#pragma unroll
    for (int q = 0; q < NPT; q++) lmin = min(lmin, key[q]);
    unsigned wmin = __reduce_min_sync(0xffffffffu, lmin);
    if (lane == 0) s_red[0][wrp] = wmin;
    __syncthreads();
    unsigned gm = __reduce_min_sync(0xffffffffu, s_red[0][lane & 7]);
    int j = (int)(gm & 1023u);

    int2* __restrict__ ep = g_edges[img];
    for (int step = 0; step < KP - 1; step++) {
        // owner records edge and marks node as in-tree
        if ((j >> 2) == tid) {
            ep[step] = make_int2(s_src[j], j);
            switch (j & 3) {
                case 0: in0 = true; key[0] = UMAXV; break;
                case 1: in1 = true; key[1] = UMAXV; break;
                case 2: in2 = true; key[2] = UMAXV; break;
                default: in3 = true; key[3] = UMAXV; break;
            }
        }
        const unsigned jxy = s_xy[j];
        const int jx = (int)(jxy >> 16), jy = (int)(jxy & 0xffffu);
        lmin = UMAXV;
#pragma unroll
        for (int q = 0; q < NPT; q++) {
            int dx = px[q] - jx, dy = py[q] - jy;
            unsigned cand = (unsigned)(dx * dx + dy * dy) * 1024u + (unsigned)(base + q);
            bool intree = (q == 0) ? in0 : (q == 1) ? in1 : (q == 2) ? in2 : in3;
            if (!intree && cand < key[q]) {    // strict <, keeps old src on tie
                key[q] = cand;
                s_src[base + q] = j;
            }
            lmin = min(lmin, key[q]);          // tree nodes hold UMAX
        }
        unsigned wm = __reduce_min_sync(0xffffffffu, lmin);
        const int par = (step + 1) & 1;        // double buffer: 1 barrier/iter
        if (lane == 0) s_red[par][wrp] = wm;
        __syncthreads();
        gm = __reduce_min_sync(0xffffffffu, s_red[par][lane & 7]);
        j = (int)(gm & 1023u);
    }
}

// ---------------- 4) per-sample loss -------------------------------------------
__device__ __forceinline__ float pdistf(float2 a, float2 b) {
    float dx = a.x - b.x, dy = a.y - b.y;
    return sqrtf(dx * dx + dy * dy);   // exact: integer d2 < 2^24
}

__global__ void loss_kernel() {
    int s = blockIdx.x;
    const float2* Pp = g_pts[2 * s];
    const float2* Pm = g_pts[2 * s + 1];
    const int2*   Ep = g_edges[2 * s];
    const int2*   Em = g_edges[2 * s + 1];

    float accP = 0.0f, accM = 0.0f;
    for (int e = threadIdx.x; e < KP - 1; e += blockDim.x) {
        int2 ep = Ep[e];
        float d1 = pdistf(Pp[ep.x], Pp[ep.y]) - pdistf(Pm[ep.x], Pm[ep.y]);
        accP += d1 * d1;
        int2 em = Em[e];
        float d2 = pdistf(Pp[em.x], Pp[em.y]) - pdistf(Pm[em.x], Pm[em.y]);
        accM += d2 * d2;
    }
    __shared__ float rp[256], rm[256];
    int tid = threadIdx.x;
    rp[tid] = accP; rm[tid] = accM;
    __syncthreads();
    for (int w = 128; w; w >>= 1) {
        if (tid < w) { rp[tid] += rp[tid + w]; rm[tid] += rm[tid + w]; }
        __syncthreads();
    }
    if (tid == 0) g_ls[s] = sqrtf(rp[0]) + sqrtf(rm[0]);
}

__global__ void final_kernel(float* out) {
    float t = 0.0f;
    for (int i = 0; i < NS; i++) t += g_ls[i];
    out[0] = 0.1f * t / 8.0f;
}

// ---------------- launch ----------------
extern "C" void kernel_launch(void* const* d_in, const int* in_sizes, int n_in,
                              void* d_out, int out_size) {
    const float* model_output = (const float*)d_in[1];
    const float* labels       = (const float*)d_in[2];
    float* out = (float*)d_out;

    lbp_kernel<<<(NIMG * HW + 255) / 256, 256>>>(model_output, labels);
    select_kernel<<<NIMG, 1024>>>();
    mst_kernel<<<NIMG, T_MST>>>();
    loss_kernel<<<NS, 256>>>();
    final_kernel<<<1, 1>>>(out);
}